// round 11
// baseline (speedup 1.0000x reference)
#include <cuda_runtime.h>

#define BB 32
#define TT 2048
#define CC 2048
#define EE 64
#define SEG 16
#define TCHUNK (TT / SEG)          // 128
#define C4 (CC / 4)                // 512
#define E4N (EE / 4)               // 16
#define TQ 128                     // t-rows per broadcast block
#define PARTS 16
#define CPART (CC / PARTS)         // 128

#define BTE (BB * TT * EE)         // 4194304 = 2^22
#define FB_OFF  BTE                // 4194304
#define LOG_OFF (BTE + 1)          // 4194305
#define MASK_OFF (BTE + 1 + BB * EE) // 4196353 (== 1 mod 4)

// Scratch (no cudaMalloc allowed)
__device__ float g_partials[SEG * BB * CC];   // 2 MB
__device__ float g_dots[BB * PARTS * EE];     // 128 KB
__device__ float g_ssum[BB * PARTS * EE];     // 128 KB
__device__ float g_sumsq[BB * PARTS];
__device__ float g_probs_seq[BB * EE];
__device__ float g_mask_seq[BB * EE];
__device__ int   g_cnt[BB];
__device__ volatile int g_flag[BB];

// ---------------------------------------------------------------------------
// Kernel 1: partial sums of hidden_states over T (split into SEG chunks).
// Plain loads (measured best: 80.1us vs 81.3 with __ldcs). 85% DRAM = at cap.
// Zeroes counters/flags/FB; the kernel boundary publishes them to k23.
// ---------------------------------------------------------------------------
__global__ void k1_partial_sums(const float* __restrict__ hs, float* __restrict__ out) {
    if (blockIdx.x == 0 && blockIdx.y == 0 && blockIdx.z == 0) {
        if (threadIdx.x == 0) out[FB_OFF] = 0.0f;
        if (threadIdx.x < BB) { g_cnt[threadIdx.x] = 0; g_flag[threadIdx.x] = 0; }
    }

    const int c4  = blockIdx.x * 256 + threadIdx.x;   // 0..511
    const int b   = blockIdx.y;
    const int seg = blockIdx.z;

    const float4* __restrict__ hs4 = (const float4*)hs;
    size_t base = ((size_t)b * TT + (size_t)seg * TCHUNK) * C4 + (size_t)c4;

    float4 acc = make_float4(0.f, 0.f, 0.f, 0.f);
#pragma unroll 8
    for (int t = 0; t < TCHUNK; ++t) {
        float4 v = hs4[base + (size_t)t * C4];
        acc.x += v.x; acc.y += v.y; acc.z += v.z; acc.w += v.w;
    }
    ((float4*)g_partials)[((size_t)seg * BB + b) * C4 + c4] = acc;
}

// ---------------------------------------------------------------------------
// Kernel 2+3 fused, 1024 blocks x 256 threads, roles by bid:
//   bid 0..511   : stage-1 gating for (part = bid>>5, b = bid&31); the 16th
//                  arriving block per b (atomic election) finishes gating
//                  (fixed-order sums -> deterministic) and raises g_flag[b].
//   bid 512..1023: broadcast chunk (b = r&31, yc = r>>5); brief spin on flag.
// Deadlock-free for ANY residency: waiters depend only on blocks that never
// wait and always retire. Low bids schedule first -> stage-1 runs first.
// ---------------------------------------------------------------------------
__global__ void __launch_bounds__(256) k23_fused(const float* __restrict__ sim,
                                                 const float* __restrict__ gates,
                                                 float* __restrict__ out) {
    __shared__ float shm[CPART > 2 * EE ? CPART : 2 * EE];  // rep_s / reuse
    __shared__ float red[128];
    __shared__ float dots4[4][EE];
    __shared__ float ss4[4][EE];
    __shared__ int   s_last;
    __shared__ float logits_s[EE];
    __shared__ float msk[EE];
    __shared__ float sm_max, sm_sum;

    const int bid = blockIdx.x;
    const int tid = threadIdx.x;

    if (bid < PARTS * BB) {
        // ==================== stage 1 ====================
        const int part = bid >> 5;
        const int b    = bid & 31;
        const int c0   = part * CPART;
        float* rep_s = shm;

        if (tid < CPART) {
            float s = 0.f;
#pragma unroll
            for (int p = 0; p < SEG; ++p)
                s += g_partials[(size_t)p * BB * CC + (size_t)b * CC + c0 + tid];
            float r = s * (1.0f / TT);
            rep_s[tid] = r;
            red[tid] = r * r;
        }
        __syncthreads();
        for (int ofs = 64; ofs > 0; ofs >>= 1) {
            if (tid < ofs) red[tid] += red[tid + ofs];
            __syncthreads();
        }
        if (tid == 0) g_sumsq[b * PARTS + part] = red[0];

        // partial dot/ss over this c-chunk: e = tid&63, 4 c-groups of 32
        const int e  = tid & (EE - 1);
        const int cg = tid >> 6;
        float dot = 0.f, ss = 0.f;
#pragma unroll 8
        for (int j = 0; j < 32; ++j) {
            int cl = cg * 32 + j;
            float sv = sim[(size_t)(c0 + cl) * EE + e];
            dot = fmaf(rep_s[cl], sv, dot);
            ss  = fmaf(sv, sv, ss);
        }
        dots4[cg][e] = dot;
        ss4[cg][e]  = ss;
        __syncthreads();

        if (tid < EE) {
            g_dots[(size_t)(b * PARTS + part) * EE + tid] =
                dots4[0][tid] + dots4[1][tid] + dots4[2][tid] + dots4[3][tid];
            g_ssum[(size_t)(b * PARTS + part) * EE + tid] =
                ss4[0][tid] + ss4[1][tid] + ss4[2][tid] + ss4[3][tid];
        }

        // ---- last-block election for b ----
        __threadfence();
        __syncthreads();
        if (tid == 0) s_last = (atomicAdd(&g_cnt[b], 1) == PARTS - 1) ? 1 : 0;
        __syncthreads();
        if (!s_last) return;

        // ==================== finish (one block per b) ====================
        float l = 0.f;
        if (tid < EE) {
            float d = 0.f, s2 = 0.f, sq = 0.f;
#pragma unroll
            for (int p = 0; p < PARTS; ++p) {
                d  += g_dots[(size_t)(b * PARTS + p) * EE + tid];
                s2 += g_ssum[(size_t)(b * PARTS + p) * EE + tid];
                sq += g_sumsq[b * PARTS + p];          // uniform -> broadcast
            }
            float nrep = fmaxf(sqrtf(sq), 1e-12f);
            float ncol = fmaxf(sqrtf(s2), 1e-12f);
            float aff  = d / (nrep * ncol);
            float gv   = gates[tid];
            float sig  = 1.0f / (1.0f + __expf(-gv));
            l = aff - sig;
            logits_s[tid] = l;
        }
        const int na = __syncthreads_count((tid < EE) && (l > 0.f));
        const int inactive = (na == 0) ? 1 : 0;

        // mask: threshold or top-32 fallback (lax.top_k tie semantics:
        // stable, lowest index wins among equals)
        if (tid < EE) {
            float m;
            if (!inactive) {
                m = (l > 0.f) ? 1.f : 0.f;
            } else {
                int rank = 0;
                for (int j = 0; j < EE; ++j) {
                    float lj = logits_s[j];
                    rank += ((lj > l) || (lj == l && j < tid)) ? 1 : 0;
                }
                m = (rank < (EE / 2)) ? 1.f : 0.f;
            }
            msk[tid] = m;
        }
        __syncthreads();

        if (tid == 0) {
            float mx = -3.402823466e+38f;
            for (int i = 0; i < EE; ++i)
                if (msk[i] > 0.f) mx = fmaxf(mx, fmaxf(logits_s[i], 0.f));
            float sum = 0.f;
            for (int i = 0; i < EE; ++i)
                if (msk[i] > 0.f) sum += __expf(fmaxf(logits_s[i], 0.f) - mx);
            sm_max = mx;
            sm_sum = sum;
            if (inactive) atomicAdd(&out[FB_OFF], 1.0f);  // integer-valued -> deterministic
        }
        __syncthreads();

        if (tid < EE) {
            float gated = fmaxf(l, 0.f);
            float p = (msk[tid] > 0.f) ? (__expf(gated - sm_max) / sm_sum) : 0.f;
            g_probs_seq[b * EE + tid] = p;
            g_mask_seq[b * EE + tid]  = msk[tid];
            out[LOG_OFF + b * EE + tid] = l;
        }
        __threadfence();
        __syncthreads();
        if (tid == 0) g_flag[b] = 1;
        return;
    }

    // ==================== broadcast ====================
    const int r  = bid - PARTS * BB;
    const int b  = r & 31;
    const int yc = r >> 5;

    if (tid == 0) {
        while (g_flag[b] == 0) { __nanosleep(64); }
    }
    __syncthreads();
    __threadfence();

    float* probs_s = shm;        // reuse shared buffer
    float* msk2    = shm + EE;
    if (tid < EE) {
        probs_s[tid] = g_probs_seq[b * EE + tid];
        msk2[tid]    = g_mask_seq[b * EE + tid];
    }
    __syncthreads();

    const int slot = tid & 15;   // 0..15
    const int trow = tid >> 4;   // 0..15

    const float4 pv = ((const float4*)probs_s)[slot];

    // mask values per slot: slot 0 -> scalars e=0,1,2,63 ; slot s>0 ->
    // aligned float4 at e=4s-1 (MASK_OFF == 1 mod 4)
    float4 mv = make_float4(0.f, 0.f, 0.f, 0.f);
    float m0 = 0.f, m1 = 0.f, m2 = 0.f, m63 = 0.f;
    if (slot == 0) { m0 = msk2[0]; m1 = msk2[1]; m2 = msk2[2]; m63 = msk2[63]; }
    else { int e = 4 * slot - 1; mv = make_float4(msk2[e], msk2[e+1], msk2[e+2], msk2[e+3]); }

    const size_t brow = (size_t)b * TT * EE;
    const int t0 = yc * TQ;

#pragma unroll
    for (int it = 0; it < TQ / 16; ++it) {
        const size_t row = brow + (size_t)(t0 + it * 16 + trow) * EE;
        __stcs((float4*)(out) + row / 4 + slot, pv);
        if (slot == 0) {
            float* d = out + MASK_OFF + row;
            __stcs(d + 0, m0); __stcs(d + 1, m1); __stcs(d + 2, m2); __stcs(d + 63, m63);
        } else {
            __stcs((float4*)(out + MASK_OFF + row + 4 * slot - 1), mv);
        }
    }
}

// ---------------------------------------------------------------------------
extern "C" void kernel_launch(void* const* d_in, const int* in_sizes, int n_in,
                              void* d_out, int out_size) {
    const float* hs    = (const float*)d_in[0];
    const float* sim   = (const float*)d_in[1];
    const float* gates = (const float*)d_in[2];
    float* out = (float*)d_out;

    k1_partial_sums<<<dim3(C4 / 256, BB, SEG), 256>>>(hs, out);
    k23_fused<<<PARTS * BB + BB * (TT / TQ), 256>>>(sim, gates, out);
}